// round 2
// baseline (speedup 1.0000x reference)
#include <cuda_runtime.h>
#include <cuda_fp16.h>
#include <math.h>

#define NNODE 100000
#define NEDGE 1600000
#define NCRYS 2000

// ---------------- static device scratch ----------------
__device__ __align__(16) float   d_x[NNODE * 64];          // node features (fp32)
__device__ __align__(16) __half2 d_Y1h[NNODE * 64];        // x@Wf_a, pairs (c, c+64)
__device__ __align__(16) __half2 d_Y2h[NNODE * 64];        // x@Wf_b, pairs (c, c+64)
__device__ __align__(16) __half2 d_zh[(size_t)NEDGE * 64]; // z pairs (c, c+64) fp16
__device__ __align__(16) float   d_acc[NNODE * 64];        // message accumulator
__device__ float  d_deg[NNODE];
__device__ double d_s[128], d_ss[128];                     // edge BN stats
__device__ float  d_a1[128], d_b1[128];                    // fused BN1: z*a+b
__device__ double d_ns[64], d_nss[64];                     // node BN stats
__device__ float  d_a2[64], d_b2[64];                      // fused BN2
__device__ __align__(16) float d_csum[NCRYS * 64];
__device__ float  d_ccnt[NCRYS];

// ---------------- helpers ----------------
static __device__ __forceinline__ unsigned long long pk2(float lo, float hi) {
    unsigned long long r;
    asm("mov.b64 %0, {%1,%2};" : "=l"(r) : "f"(lo), "f"(hi));
    return r;
}
static __device__ __forceinline__ float2 upk2(unsigned long long v) {
    float2 r;
    asm("mov.b64 {%0,%1}, %2;" : "=f"(r.x), "=f"(r.y) : "l"(v));
    return r;
}
static __device__ __forceinline__ unsigned long long ffma2(unsigned long long a, unsigned long long b, unsigned long long c) {
    unsigned long long d;
    asm("fma.rn.f32x2 %0, %1, %2, %3;" : "=l"(d) : "l"(a), "l"(b), "l"(c));
    return d;
}
static __device__ __forceinline__ __half2 u2h(unsigned int v) {
    return *reinterpret_cast<__half2*>(&v);
}
static __device__ __forceinline__ unsigned int h2u(__half2 h) {
    return *reinterpret_cast<unsigned int*>(&h);
}
__device__ __forceinline__ float sp_(float v) {  // softplus, stable
    return fmaxf(v, 0.f) + log1pf(__expf(-fabsf(v)));
}
__device__ __forceinline__ float sg_(float v) {  // sigmoid
    return 1.f / (1.f + __expf(-v));
}

// ---------------- kernels ----------------
__global__ void k_zero_once() {
    int i = blockIdx.x * blockDim.x + threadIdx.x;
    int stride = gridDim.x * blockDim.x;
    for (; i < NCRYS * 64; i += stride) {
        d_csum[i] = 0.f;
        if (i < NNODE) d_deg[i] = 0.f;
        if (i < NCRYS) d_ccnt[i] = 0.f;
    }
}

__global__ void k_zero_layer(int N) {
    int i = blockIdx.x * blockDim.x + threadIdx.x;
    int stride = gridDim.x * blockDim.x;
    for (; i < N * 64; i += stride) {
        d_acc[i] = 0.f;
        if (i < 128) { d_s[i] = 0.0; d_ss[i] = 0.0; }
        if (i < 64)  { d_ns[i] = 0.0; d_nss[i] = 0.0; }
    }
}

__global__ void k_embed(const int* __restrict__ node_fea, const float* __restrict__ emb, int N) {
    int i = blockIdx.x * blockDim.x + threadIdx.x;
    if (i < N * 64) {
        int n = i >> 6, c = i & 63;
        d_x[i] = emb[node_fea[n] * 64 + c];
    }
}

__global__ void k_deg(const int* __restrict__ idx1, int E) {
    int e = blockIdx.x * blockDim.x + threadIdx.x;
    if (e < E) atomicAdd(&d_deg[idx1[e]], 1.0f);
}

// Y1 = x @ Wf[l][0:64,:],  Y2 = x @ Wf[l][64:128,:]   -> fp16 pairs (c, c+64)
__global__ void k_nodegemm(const float* __restrict__ Wf, int l, int N) {
    const int NB = 32;
    __shared__ float xs[NB][64];
    __shared__ float outs[NB][256];
    int n0 = blockIdx.x * NB;
    int t = threadIdx.x;

    for (int idx = t; idx < NB * 64; idx += 256) {
        int m = idx >> 6, k = idx & 63;
        xs[m][k] = (n0 + m < N) ? d_x[(size_t)(n0 + m) * 64 + k] : 0.f;
    }
    __syncthreads();

    int part = t >> 7;       // 0 -> Y1, 1 -> Y2
    int j = t & 127;         // output column
    const float* wbase = Wf + (size_t)(l * 169 + part * 64) * 128 + j;
    float Wreg[64];
#pragma unroll
    for (int k = 0; k < 64; k++) Wreg[k] = wbase[(size_t)k * 128];

    for (int m = 0; m < NB; m++) {
        float a = 0.f;
#pragma unroll
        for (int k = 0; k < 64; k++) a += xs[m][k] * Wreg[k];
        outs[m][t] = a;
    }
    __syncthreads();

    for (int idx = t; idx < NB * 128; idx += 256) {
        int m = idx >> 7, r = idx & 127;
        int mat = r >> 6, cp = r & 63;
        int n = n0 + m;
        if (n < N) {
            float lo = outs[m][mat * 128 + cp];
            float hi = outs[m][mat * 128 + cp + 64];
            __half2 v = __floats2half2_rn(lo, hi);
            if (mat) d_Y2h[(size_t)n * 64 + cp] = v;
            else     d_Y1h[(size_t)n * 64 + cp] = v;
        }
    }
}

// pass 1: z = Y1[i1] + Y2[i2] + ef@Wf_e + bf ; store z pairs (fp16) ; accumulate stats
// Register-tiled: each thread computes 4 edges x 4 column-pairs. Persistent blocks,
// BN stats accumulated in registers, one block reduction + few atomics at the end.
__global__ void __launch_bounds__(256) k_edge1(
        const float* __restrict__ edge_fea,
        const int* __restrict__ idx1, const int* __restrict__ idx2,
        const float* __restrict__ Wf, const float* __restrict__ bf,
        int l, int E, int nchunk) {
    __shared__ float ef_s[128][41];              // 21 KB, reused as reduction buffer
    __shared__ unsigned long long Wp_s[64][41];  // 21 KB, pairs (c, c+64), [pair][k]
    __shared__ int i1_s[128], i2_s[128];

    int t = threadIdx.x;
    int cg = t & 15;      // column group: cpairs 4cg..4cg+3
    int eg = t >> 4;      // edge group: 8 edges 8eg..8eg+7 (two passes of 4)

    // Load edge-weight pairs into shared (persistent across chunks)
    const float* wbase = Wf + (size_t)(l * 169 + 128) * 128;
    for (int idx = t; idx < 64 * 41; idx += 256) {
        int p = idx / 41, k = idx - p * 41;
        Wp_s[p][k] = pk2(wbase[k * 128 + p], wbase[k * 128 + p + 64]);
    }
    float blo[4], bhi[4];
#pragma unroll
    for (int v = 0; v < 4; v++) {
        int c = 4 * cg + v;
        blo[v] = bf[l * 128 + c];
        bhi[v] = bf[l * 128 + c + 64];
    }

    float sx[4] = {0,0,0,0}, sy[4] = {0,0,0,0}, qx[4] = {0,0,0,0}, qy[4] = {0,0,0,0};

    for (int chunk = blockIdx.x; chunk < nchunk; chunk += gridDim.x) {
        int e0 = chunk * 128;
        __syncthreads();
        for (int idx = t; idx < 128 * 41; idx += 256) {
            int el = idx / 41, k = idx - el * 41;
            int e = e0 + el;
            ef_s[el][k] = (e < E) ? edge_fea[(size_t)e * 41 + k] : 0.f;
        }
        if (t < 128) {
            int e = e0 + t;
            i1_s[t] = (e < E) ? idx1[e] : 0;
            i2_s[t] = (e < E) ? idx2[e] : 0;
        }
        __syncthreads();

#pragma unroll
        for (int pass = 0; pass < 2; pass++) {
            int elb = eg * 8 + pass * 4;
            unsigned long long acc[4][4];
#pragma unroll
            for (int u = 0; u < 4; u++) {
                int el = elb + u;
                int n1 = i1_s[el], n2 = i2_s[el];
                uint4 q1 = *reinterpret_cast<const uint4*>(&d_Y1h[(size_t)n1 * 64 + 4 * cg]);
                uint4 q2 = *reinterpret_cast<const uint4*>(&d_Y2h[(size_t)n2 * 64 + 4 * cg]);
                float2 a0 = __half22float2(u2h(q1.x)), b0 = __half22float2(u2h(q2.x));
                float2 a1 = __half22float2(u2h(q1.y)), b1 = __half22float2(u2h(q2.y));
                float2 a2 = __half22float2(u2h(q1.z)), b2 = __half22float2(u2h(q2.z));
                float2 a3 = __half22float2(u2h(q1.w)), b3 = __half22float2(u2h(q2.w));
                acc[u][0] = pk2(a0.x + b0.x + blo[0], a0.y + b0.y + bhi[0]);
                acc[u][1] = pk2(a1.x + b1.x + blo[1], a1.y + b1.y + bhi[1]);
                acc[u][2] = pk2(a2.x + b2.x + blo[2], a2.y + b2.y + bhi[2]);
                acc[u][3] = pk2(a3.x + b3.x + blo[3], a3.y + b3.y + bhi[3]);
            }
#pragma unroll
            for (int k = 0; k < 41; k++) {
                unsigned long long ep[4], wp[4];
#pragma unroll
                for (int u = 0; u < 4; u++) {
                    float v_ = ef_s[elb + u][k];
                    ep[u] = pk2(v_, v_);
                }
#pragma unroll
                for (int v = 0; v < 4; v++) wp[v] = Wp_s[4 * cg + v][k];
#pragma unroll
                for (int u = 0; u < 4; u++)
#pragma unroll
                    for (int v = 0; v < 4; v++)
                        acc[u][v] = ffma2(ep[u], wp[v], acc[u][v]);
            }
#pragma unroll
            for (int u = 0; u < 4; u++) {
                int e = e0 + elb + u;
                if (e < E) {
                    float2 a0 = upk2(acc[u][0]);
                    float2 a1 = upk2(acc[u][1]);
                    float2 a2 = upk2(acc[u][2]);
                    float2 a3 = upk2(acc[u][3]);
                    uint4 st;
                    st.x = h2u(__floats2half2_rn(a0.x, a0.y));
                    st.y = h2u(__floats2half2_rn(a1.x, a1.y));
                    st.z = h2u(__floats2half2_rn(a2.x, a2.y));
                    st.w = h2u(__floats2half2_rn(a3.x, a3.y));
                    __stcs(reinterpret_cast<uint4*>(&d_zh[(size_t)e * 64 + 4 * cg]), st);
                    sx[0] += a0.x; sy[0] += a0.y; qx[0] += a0.x * a0.x; qy[0] += a0.y * a0.y;
                    sx[1] += a1.x; sy[1] += a1.y; qx[1] += a1.x * a1.x; qy[1] += a1.y * a1.y;
                    sx[2] += a2.x; sy[2] += a2.y; qx[2] += a2.x * a2.x; qy[2] += a2.y * a2.y;
                    sx[3] += a3.x; sy[3] += a3.y; qx[3] += a3.x * a3.x; qy[3] += a3.y * a3.y;
                }
            }
        }
    }

    // ---- block reduction of stats, few atomics ----
    __syncthreads();
    float (*red)[128] = reinterpret_cast<float (*)[128]>(&ef_s[0][0]);
#pragma unroll
    for (int v = 0; v < 4; v++) {
        red[eg][4 * cg + v] = sx[v];
        red[eg][64 + 4 * cg + v] = sy[v];
    }
    __syncthreads();
    if (t < 128) {
        float s = 0.f;
#pragma unroll
        for (int g = 0; g < 16; g++) s += red[g][t];
        atomicAdd(&d_s[t], (double)s);
    }
    __syncthreads();
#pragma unroll
    for (int v = 0; v < 4; v++) {
        red[eg][4 * cg + v] = qx[v];
        red[eg][64 + 4 * cg + v] = qy[v];
    }
    __syncthreads();
    if (t < 128) {
        float s = 0.f;
#pragma unroll
        for (int g = 0; g < 16; g++) s += red[g][t];
        atomicAdd(&d_ss[t], (double)s);
    }
}

__global__ void k_fin1(const float* __restrict__ g1, const float* __restrict__ be1, int l, int E) {
    int c = threadIdx.x;  // 128
    double mean = d_s[c] / (double)E;
    double var = d_ss[c] / (double)E - mean * mean;
    float rstd = (float)(1.0 / sqrt(var + 1e-5));
    float a = g1[l * 128 + c] * rstd;
    d_a1[c] = a;
    d_b1[c] = be1[l * 128 + c] - (float)mean * a;
}

// pass 2: msg = sigmoid(bn(gate)) * softplus(bn(conv)); scatter-add by idx1
__global__ void k_edge2(const int* __restrict__ idx1, int E) {
    const int CH = 128;
    int e0 = blockIdx.x * CH;
    int t = threadIdx.x;           // 256
    int c4 = t & 15;               // column quad: cols 4c4..4c4+3 (and +64 partners)
    int lane = t >> 4;             // 16 edge lanes

    float ag[4], bg[4], ac[4], bc[4];
#pragma unroll
    for (int u = 0; u < 4; u++) {
        ag[u] = d_a1[4 * c4 + u];      bg[u] = d_b1[4 * c4 + u];
        ac[u] = d_a1[64 + 4 * c4 + u]; bc[u] = d_b1[64 + 4 * c4 + u];
    }

    for (int i = lane; i < CH; i += 16) {
        int e = e0 + i;
        if (e >= E) break;
        uint4 zq = __ldcs(reinterpret_cast<const uint4*>(&d_zh[(size_t)e * 64 + 4 * c4]));
        float2 z0 = __half22float2(u2h(zq.x));
        float2 z1 = __half22float2(u2h(zq.y));
        float2 z2 = __half22float2(u2h(zq.z));
        float2 z3 = __half22float2(u2h(zq.w));
        float m0 = sg_(z0.x * ag[0] + bg[0]) * sp_(z0.y * ac[0] + bc[0]);
        float m1 = sg_(z1.x * ag[1] + bg[1]) * sp_(z1.y * ac[1] + bc[1]);
        float m2 = sg_(z2.x * ag[2] + bg[2]) * sp_(z2.y * ac[2] + bc[2]);
        float m3 = sg_(z3.x * ag[3] + bg[3]) * sp_(z3.y * ac[3] + bc[3]);
        int n = __ldg(&idx1[e]);
        float* p = &d_acc[(size_t)n * 64 + 4 * c4];
        asm volatile("red.global.add.v4.f32 [%0], {%1,%2,%3,%4};"
                     :: "l"(p), "f"(m0), "f"(m1), "f"(m2), "f"(m3) : "memory");
    }
}

__global__ void k_nodestats(int N) {
    int t = threadIdx.x;       // 256
    int c = t & 63, nl = t >> 6;
    float s = 0.f, q = 0.f;
    for (int n = blockIdx.x * 4 + nl; n < N; n += gridDim.x * 4) {
        float rdeg = 1.f / fmaxf(d_deg[n], 1.f);
        float v = d_acc[(size_t)n * 64 + c] * rdeg;
        s += v; q += v * v;
    }
    atomicAdd(&d_ns[c], (double)s);
    atomicAdd(&d_nss[c], (double)q);
}

__global__ void k_fin2(const float* __restrict__ g2, const float* __restrict__ be2, int l, int N) {
    int c = threadIdx.x;  // 64
    double mean = d_ns[c] / (double)N;
    double var = d_nss[c] / (double)N - mean * mean;
    float rstd = (float)(1.0 / sqrt(var + 1e-5));
    float a = g2[l * 64 + c] * rstd;
    d_a2[c] = a;
    d_b2[c] = be2[l * 64 + c] - (float)mean * a;
}

__global__ void k_nodeupd(int N) {
    int i = blockIdx.x * blockDim.x + threadIdx.x;
    if (i < N * 64) {
        int n = i >> 6, c = i & 63;
        float rdeg = 1.f / fmaxf(d_deg[n], 1.f);
        float nv = d_acc[i] * rdeg * d_a2[c] + d_b2[c];
        d_x[i] = sp_(d_x[i] + nv);
    }
}

__global__ void k_crys(const int* __restrict__ idx3, int N) {
    int g = blockIdx.x * blockDim.x + threadIdx.x;
    if (g < N * 16) {
        int n = g >> 4, c4 = g & 15;
        int cr = idx3[n];
        float4 v = *reinterpret_cast<const float4*>(&d_x[(size_t)n * 64 + c4 * 4]);
        float* p = &d_csum[(size_t)cr * 64 + c4 * 4];
        asm volatile("red.global.add.v4.f32 [%0], {%1,%2,%3,%4};"
                     :: "l"(p), "f"(v.x), "f"(v.y), "f"(v.z), "f"(v.w) : "memory");
        if (c4 == 0) atomicAdd(&d_ccnt[cr], 1.0f);
    }
}

__global__ void k_head(const float* __restrict__ Wc, const float* __restrict__ bcv,
                       const float* __restrict__ Wo, const float* __restrict__ bo,
                       float* __restrict__ out, int C) {
    __shared__ float cs[64];
    __shared__ float r0[128], r1[128];
    int ci = blockIdx.x;
    int t = threadIdx.x;  // 128
    if (t < 64) cs[t] = d_csum[(size_t)ci * 64 + t] / fmaxf(d_ccnt[ci], 1.f);
    __syncthreads();
    float h = bcv[t];
#pragma unroll
    for (int k = 0; k < 64; k++) h += cs[k] * Wc[k * 128 + t];
    h = sp_(h);
    r0[t] = h * Wo[t * 2];
    r1[t] = h * Wo[t * 2 + 1];
    __syncthreads();
    for (int s = 64; s > 0; s >>= 1) {
        if (t < s) { r0[t] += r0[t + s]; r1[t] += r1[t + s]; }
        __syncthreads();
    }
    if (t == 0) {
        out[ci * 2 + 0] = r0[0] + bo[0];
        out[ci * 2 + 1] = r1[0] + bo[1];
    }
}

// ---------------- launch ----------------
extern "C" void kernel_launch(void* const* d_in, const int* in_sizes, int n_in,
                              void* d_out, int out_size) {
    const int*   node_fea = (const int*)d_in[0];
    const float* edge_fea = (const float*)d_in[1];
    const int*   idx1 = (const int*)d_in[2];
    const int*   idx2 = (const int*)d_in[3];
    const int*   idx3 = (const int*)d_in[4];
    const float* emb  = (const float*)d_in[5];
    const float* Wf   = (const float*)d_in[6];
    const float* bf   = (const float*)d_in[7];
    const float* g1   = (const float*)d_in[8];
    const float* be1  = (const float*)d_in[9];
    const float* g2   = (const float*)d_in[10];
    const float* be2  = (const float*)d_in[11];
    const float* Wc   = (const float*)d_in[12];
    const float* bcv  = (const float*)d_in[13];
    const float* Wo   = (const float*)d_in[14];
    const float* bo   = (const float*)d_in[15];
    float* out = (float*)d_out;

    int N = in_sizes[0];
    int E = in_sizes[2];
    int C = out_size / 2;
    int nchunk = (E + 127) / 128;

    k_zero_once<<<512, 256>>>();
    k_embed<<<(N * 64 + 255) / 256, 256>>>(node_fea, emb, N);
    k_deg<<<(E + 255) / 256, 256>>>(idx1, E);

    for (int l = 0; l < 3; l++) {
        k_zero_layer<<<(N * 64 + 255) / 256, 256>>>(N);
        k_nodegemm<<<(N + 31) / 32, 256>>>(Wf, l, N);
        k_edge1<<<592, 256>>>(edge_fea, idx1, idx2, Wf, bf, l, E, nchunk);
        k_fin1<<<1, 128>>>(g1, be1, l, E);
        k_edge2<<<(E + 127) / 128, 256>>>(idx1, E);
        k_nodestats<<<256, 256>>>(N);
        k_fin2<<<1, 64>>>(g2, be2, l, N);
        k_nodeupd<<<(N * 64 + 255) / 256, 256>>>(N);
    }

    k_crys<<<(N * 16 + 255) / 256, 256>>>(idx3, N);
    k_head<<<C, 128>>>(Wc, bcv, Wo, bo, out, C);
}

// round 5
// speedup vs baseline: 1.4759x; 1.4759x over previous
#include <cuda_runtime.h>
#include <cuda_fp16.h>
#include <math.h>

#define NNODE 100000
#define NEDGE 1600000
#define NCRYS 2000

// ---------------- static device scratch ----------------
__device__ __align__(16) float   d_x[NNODE * 64];          // node features (fp32)
__device__ __align__(16) __half2 d_Y1h[NNODE * 64];        // x@Wf_a, pairs (c, c+64)
__device__ __align__(16) __half2 d_Y2h[NNODE * 64];        // x@Wf_b, pairs (c, c+64)
__device__ __align__(16) __half2 d_zh[(size_t)NEDGE * 64]; // z pairs (c, c+64) fp16
__device__ __align__(16) float   d_acc[NNODE * 64];        // message accumulator
__device__ float  d_deg[NNODE];
__device__ double d_s[128], d_ss[128];                     // edge BN stats
__device__ float  d_a1[128], d_b1[128];                    // fused BN1: z*a+b
__device__ double d_ns[64], d_nss[64];                     // node BN stats
__device__ float  d_a2[64], d_b2[64];                      // fused BN2
__device__ __align__(16) float d_csum[NCRYS * 64];
__device__ float  d_ccnt[NCRYS];

// ---------------- helpers ----------------
static __device__ __forceinline__ unsigned long long pk2(float lo, float hi) {
    unsigned long long r;
    asm("mov.b64 %0, {%1,%2};" : "=l"(r) : "f"(lo), "f"(hi));
    return r;
}
static __device__ __forceinline__ float2 upk2(unsigned long long v) {
    float2 r;
    asm("mov.b64 {%0,%1}, %2;" : "=f"(r.x), "=f"(r.y) : "l"(v));
    return r;
}
static __device__ __forceinline__ unsigned long long ffma2(unsigned long long a, unsigned long long b, unsigned long long c) {
    unsigned long long d;
    asm("fma.rn.f32x2 %0, %1, %2, %3;" : "=l"(d) : "l"(a), "l"(b), "l"(c));
    return d;
}
static __device__ __forceinline__ __half2 u2h(unsigned int v) {
    return *reinterpret_cast<__half2*>(&v);
}
static __device__ __forceinline__ unsigned int h2u(__half2 h) {
    return *reinterpret_cast<unsigned int*>(&h);
}
__device__ __forceinline__ float sp_(float v) {  // softplus, stable
    return fmaxf(v, 0.f) + log1pf(__expf(-fabsf(v)));
}
__device__ __forceinline__ float sg_(float v) {  // sigmoid
    return 1.f / (1.f + __expf(-v));
}

// ---------------- kernels ----------------
__global__ void k_init() {  // zero everything needed before layer 0
    int i = blockIdx.x * blockDim.x + threadIdx.x;
    int stride = gridDim.x * blockDim.x;
    for (; i < NNODE * 64; i += stride) {
        d_acc[i] = 0.f;
        if (i < NCRYS * 64) d_csum[i] = 0.f;
        if (i < NNODE) d_deg[i] = 0.f;
        if (i < NCRYS) d_ccnt[i] = 0.f;
        if (i < 128) { d_s[i] = 0.0; d_ss[i] = 0.0; }
        if (i < 64)  { d_ns[i] = 0.0; d_nss[i] = 0.0; }
    }
}

__global__ void k_embed(const int* __restrict__ node_fea, const float* __restrict__ emb, int N) {
    int i = blockIdx.x * blockDim.x + threadIdx.x;
    if (i < N * 64) {
        int n = i >> 6, c = i & 63;
        d_x[i] = emb[node_fea[n] * 64 + c];
    }
}

__global__ void k_deg(const int* __restrict__ idx1, int E) {
    int e = blockIdx.x * blockDim.x + threadIdx.x;
    if (e < E) atomicAdd(&d_deg[idx1[e]], 1.0f);
}

// Y1 = x @ Wf[l][0:64,:],  Y2 = x @ Wf[l][64:128,:]   -> fp16 pairs (c, c+64)
__global__ void k_nodegemm(const float* __restrict__ Wf, int l, int N) {
    const int NB = 32;
    __shared__ float xs[NB][64];
    __shared__ float outs[NB][256];
    int n0 = blockIdx.x * NB;
    int t = threadIdx.x;

    for (int idx = t; idx < NB * 64; idx += 256) {
        int m = idx >> 6, k = idx & 63;
        xs[m][k] = (n0 + m < N) ? d_x[(size_t)(n0 + m) * 64 + k] : 0.f;
    }
    __syncthreads();

    int part = t >> 7;       // 0 -> Y1, 1 -> Y2
    int j = t & 127;         // output column
    const float* wbase = Wf + (size_t)(l * 169 + part * 64) * 128 + j;
    float Wreg[64];
#pragma unroll
    for (int k = 0; k < 64; k++) Wreg[k] = wbase[(size_t)k * 128];

    for (int m = 0; m < NB; m++) {
        float a = 0.f;
#pragma unroll
        for (int k = 0; k < 64; k++) a += xs[m][k] * Wreg[k];
        outs[m][t] = a;
    }
    __syncthreads();

    for (int idx = t; idx < NB * 128; idx += 256) {
        int m = idx >> 7, r = idx & 127;
        int mat = r >> 6, cp = r & 63;
        int n = n0 + m;
        if (n < N) {
            float lo = outs[m][mat * 128 + cp];
            float hi = outs[m][mat * 128 + cp + 64];
            __half2 v = __floats2half2_rn(lo, hi);
            if (mat) d_Y2h[(size_t)n * 64 + cp] = v;
            else     d_Y1h[(size_t)n * 64 + cp] = v;
        }
    }
}

// pass 1: z = Y1[i1] + Y2[i2] + ef@Wf_e + bf ; store z pairs (fp16) ; stats in regs.
// 2-edge x 2-colpair register tile. Weights k-major in shared -> one conflict-free
// LDS.128 per k. ef pre-duplicated (v,v) u64 -> broadcast LDS.64.
__global__ void __launch_bounds__(256) k_edge1(
        const float* __restrict__ edge_fea,
        const int* __restrict__ idx1, const int* __restrict__ idx2,
        const float* __restrict__ Wf, const float* __restrict__ bf,
        int l, int E, int nchunk) {
    __shared__ unsigned long long efp[64][41];   // 20.5 KB  (v,v) pairs
    __shared__ unsigned long long Wu[41][64];    // 20.5 KB  k-major pairs (c, c+64)
    __shared__ int i1_s[64], i2_s[64];
    __shared__ float red_s[8][128];              // 4 KB stats reduction

    int t = threadIdx.x;
    int c2 = t & 31;      // column-pair group: pairs 2c2, 2c2+1
    int el = t >> 5;      // edge lane 0..7

    // weights -> shared, k-major (persistent across chunks)
    const float* wbase = Wf + (size_t)(l * 169 + 128) * 128;
    for (int idx = t; idx < 41 * 64; idx += 256) {
        int k = idx >> 6, p = idx & 63;
        Wu[k][p] = pk2(wbase[k * 128 + p], wbase[k * 128 + p + 64]);
    }
    float blo0 = bf[l * 128 + 2 * c2],     bhi0 = bf[l * 128 + 2 * c2 + 64];
    float blo1 = bf[l * 128 + 2 * c2 + 1], bhi1 = bf[l * 128 + 2 * c2 + 65];

    float sx0 = 0.f, sx1 = 0.f, sy0 = 0.f, sy1 = 0.f;
    float qx0 = 0.f, qx1 = 0.f, qy0 = 0.f, qy1 = 0.f;

    for (int chunk = blockIdx.x; chunk < nchunk; chunk += gridDim.x) {
        int e0 = chunk * 64;
        __syncthreads();
        for (int idx = t; idx < 64 * 41; idx += 256) {
            int ee = idx / 41, k = idx - ee * 41;
            int e = e0 + ee;
            float v = (e < E) ? edge_fea[(size_t)e * 41 + k] : 0.f;
            efp[ee][k] = pk2(v, v);
        }
        if (t < 64) {
            int e = e0 + t;
            i1_s[t] = (e < E) ? idx1[e] : 0;
            i2_s[t] = (e < E) ? idx2[e] : 0;
        }
        __syncthreads();

#pragma unroll
        for (int it = 0; it < 4; it++) {
            int ea = el * 8 + it * 2;
            int eb = ea + 1;
            int n1a = i1_s[ea], n2a = i2_s[ea];
            int n1b = i1_s[eb], n2b = i2_s[eb];

            uint2 qa1 = *reinterpret_cast<const uint2*>(&d_Y1h[(size_t)n1a * 64 + 2 * c2]);
            uint2 qa2 = *reinterpret_cast<const uint2*>(&d_Y2h[(size_t)n2a * 64 + 2 * c2]);
            uint2 qb1 = *reinterpret_cast<const uint2*>(&d_Y1h[(size_t)n1b * 64 + 2 * c2]);
            uint2 qb2 = *reinterpret_cast<const uint2*>(&d_Y2h[(size_t)n2b * 64 + 2 * c2]);

            float2 pa0 = __half22float2(u2h(qa1.x)), ra0 = __half22float2(u2h(qa2.x));
            float2 pa1 = __half22float2(u2h(qa1.y)), ra1 = __half22float2(u2h(qa2.y));
            float2 pb0 = __half22float2(u2h(qb1.x)), rb0 = __half22float2(u2h(qb2.x));
            float2 pb1 = __half22float2(u2h(qb1.y)), rb1 = __half22float2(u2h(qb2.y));

            unsigned long long a00 = pk2(pa0.x + ra0.x + blo0, pa0.y + ra0.y + bhi0);
            unsigned long long a01 = pk2(pa1.x + ra1.x + blo1, pa1.y + ra1.y + bhi1);
            unsigned long long a10 = pk2(pb0.x + rb0.x + blo0, pb0.y + rb0.y + bhi0);
            unsigned long long a11 = pk2(pb1.x + rb1.x + blo1, pb1.y + rb1.y + bhi1);

#pragma unroll
            for (int k = 0; k < 41; k++) {
                ulonglong2 w = *reinterpret_cast<const ulonglong2*>(&Wu[k][2 * c2]);
                unsigned long long fa = efp[ea][k];
                unsigned long long fb = efp[eb][k];
                a00 = ffma2(fa, w.x, a00);
                a01 = ffma2(fa, w.y, a01);
                a10 = ffma2(fb, w.x, a10);
                a11 = ffma2(fb, w.y, a11);
            }

            float2 v00 = upk2(a00), v01 = upk2(a01), v10 = upk2(a10), v11 = upk2(a11);
            int eag = e0 + ea, ebg = e0 + eb;
            if (eag < E) {
                uint2 st;
                st.x = h2u(__floats2half2_rn(v00.x, v00.y));
                st.y = h2u(__floats2half2_rn(v01.x, v01.y));
                __stcs(reinterpret_cast<uint2*>(&d_zh[(size_t)eag * 64 + 2 * c2]), st);
                sx0 += v00.x; sy0 += v00.y; qx0 += v00.x * v00.x; qy0 += v00.y * v00.y;
                sx1 += v01.x; sy1 += v01.y; qx1 += v01.x * v01.x; qy1 += v01.y * v01.y;
            }
            if (ebg < E) {
                uint2 st;
                st.x = h2u(__floats2half2_rn(v10.x, v10.y));
                st.y = h2u(__floats2half2_rn(v11.x, v11.y));
                __stcs(reinterpret_cast<uint2*>(&d_zh[(size_t)ebg * 64 + 2 * c2]), st);
                sx0 += v10.x; sy0 += v10.y; qx0 += v10.x * v10.x; qy0 += v10.y * v10.y;
                sx1 += v11.x; sy1 += v11.y; qx1 += v11.x * v11.x; qy1 += v11.y * v11.y;
            }
        }
    }

    // ---- block reduction of stats -> few double atomics ----
    __syncthreads();
    red_s[el][2 * c2 + 0] = sx0;
    red_s[el][2 * c2 + 1] = sx1;
    red_s[el][64 + 2 * c2 + 0] = sy0;
    red_s[el][64 + 2 * c2 + 1] = sy1;
    __syncthreads();
    if (t < 128) {
        float s = 0.f;
#pragma unroll
        for (int g = 0; g < 8; g++) s += red_s[g][t];
        atomicAdd(&d_s[t], (double)s);
    }
    __syncthreads();
    red_s[el][2 * c2 + 0] = qx0;
    red_s[el][2 * c2 + 1] = qx1;
    red_s[el][64 + 2 * c2 + 0] = qy0;
    red_s[el][64 + 2 * c2 + 1] = qy1;
    __syncthreads();
    if (t < 128) {
        float s = 0.f;
#pragma unroll
        for (int g = 0; g < 8; g++) s += red_s[g][t];
        atomicAdd(&d_ss[t], (double)s);
    }
}

__global__ void k_fin1(const float* __restrict__ g1, const float* __restrict__ be1, int l, int E) {
    int c = threadIdx.x;  // 128
    double mean = d_s[c] / (double)E;
    double var = d_ss[c] / (double)E - mean * mean;
    float rstd = (float)(1.0 / sqrt(var + 1e-5));
    float a = g1[l * 128 + c] * rstd;
    d_a1[c] = a;
    d_b1[c] = be1[l * 128 + c] - (float)mean * a;
}

// pass 2: msg = sigmoid(bn(gate)) * softplus(bn(conv)); scatter-add by idx1
__global__ void k_edge2(const int* __restrict__ idx1, int E) {
    const int CH = 128;
    int e0 = blockIdx.x * CH;
    int t = threadIdx.x;           // 256
    int c4 = t & 15;               // column quad: pairs 4c4..4c4+3
    int lane = t >> 4;             // 16 edge lanes

    float ag[4], bg[4], ac[4], bc[4];
#pragma unroll
    for (int u = 0; u < 4; u++) {
        ag[u] = d_a1[4 * c4 + u];      bg[u] = d_b1[4 * c4 + u];
        ac[u] = d_a1[64 + 4 * c4 + u]; bc[u] = d_b1[64 + 4 * c4 + u];
    }

    for (int i = lane; i < CH; i += 16) {
        int e = e0 + i;
        if (e >= E) break;
        uint4 zq = __ldcs(reinterpret_cast<const uint4*>(&d_zh[(size_t)e * 64 + 4 * c4]));
        float2 z0 = __half22float2(u2h(zq.x));
        float2 z1 = __half22float2(u2h(zq.y));
        float2 z2 = __half22float2(u2h(zq.z));
        float2 z3 = __half22float2(u2h(zq.w));
        float m0 = sg_(z0.x * ag[0] + bg[0]) * sp_(z0.y * ac[0] + bc[0]);
        float m1 = sg_(z1.x * ag[1] + bg[1]) * sp_(z1.y * ac[1] + bc[1]);
        float m2 = sg_(z2.x * ag[2] + bg[2]) * sp_(z2.y * ac[2] + bc[2]);
        float m3 = sg_(z3.x * ag[3] + bg[3]) * sp_(z3.y * ac[3] + bc[3]);
        int n = __ldg(&idx1[e]);
        float* p = &d_acc[(size_t)n * 64 + 4 * c4];
        asm volatile("red.global.add.v4.f32 [%0], {%1,%2,%3,%4};"
                     :: "l"(p), "f"(m0), "f"(m1), "f"(m2), "f"(m3) : "memory");
    }
}

__global__ void k_nodestats(int N) {
    int t = threadIdx.x;       // 256
    int c = t & 63, nl = t >> 6;
    float s = 0.f, q = 0.f;
    for (int n = blockIdx.x * 4 + nl; n < N; n += gridDim.x * 4) {
        float rdeg = 1.f / fmaxf(d_deg[n], 1.f);
        float v = d_acc[(size_t)n * 64 + c] * rdeg;
        s += v; q += v * v;
    }
    atomicAdd(&d_ns[c], (double)s);
    atomicAdd(&d_nss[c], (double)q);
}

__global__ void k_fin2(const float* __restrict__ g2, const float* __restrict__ be2, int l, int N) {
    int c = threadIdx.x;  // 64
    double mean = d_ns[c] / (double)N;
    double var = d_nss[c] / (double)N - mean * mean;
    float rstd = (float)(1.0 / sqrt(var + 1e-5));
    float a = g2[l * 64 + c] * rstd;
    d_a2[c] = a;
    d_b2[c] = be2[l * 64 + c] - (float)mean * a;
}

// node update; also re-zeros d_acc and the stat accumulators for the next layer
__global__ void k_nodeupd(int N) {
    int i = blockIdx.x * blockDim.x + threadIdx.x;
    if (i < N * 64) {
        int n = i >> 6, c = i & 63;
        float rdeg = 1.f / fmaxf(d_deg[n], 1.f);
        float nv = d_acc[i] * rdeg * d_a2[c] + d_b2[c];
        d_x[i] = sp_(d_x[i] + nv);
        d_acc[i] = 0.f;
        if (i < 128) { d_s[i] = 0.0; d_ss[i] = 0.0; }
        if (i < 64)  { d_ns[i] = 0.0; d_nss[i] = 0.0; }
    }
}

__global__ void k_crys(const int* __restrict__ idx3, int N) {
    int g = blockIdx.x * blockDim.x + threadIdx.x;
    if (g < N * 16) {
        int n = g >> 4, c4 = g & 15;
        int cr = idx3[n];
        float4 v = *reinterpret_cast<const float4*>(&d_x[(size_t)n * 64 + c4 * 4]);
        float* p = &d_csum[(size_t)cr * 64 + c4 * 4];
        asm volatile("red.global.add.v4.f32 [%0], {%1,%2,%3,%4};"
                     :: "l"(p), "f"(v.x), "f"(v.y), "f"(v.z), "f"(v.w) : "memory");
        if (c4 == 0) atomicAdd(&d_ccnt[cr], 1.0f);
    }
}

__global__ void k_head(const float* __restrict__ Wc, const float* __restrict__ bcv,
                       const float* __restrict__ Wo, const float* __restrict__ bo,
                       float* __restrict__ out, int C) {
    __shared__ float cs[64];
    __shared__ float r0[128], r1[128];
    int ci = blockIdx.x;
    int t = threadIdx.x;  // 128
    if (t < 64) cs[t] = d_csum[(size_t)ci * 64 + t] / fmaxf(d_ccnt[ci], 1.f);
    __syncthreads();
    float h = bcv[t];
#pragma unroll
    for (int k = 0; k < 64; k++) h += cs[k] * Wc[k * 128 + t];
    h = sp_(h);
    r0[t] = h * Wo[t * 2];
    r1[t] = h * Wo[t * 2 + 1];
    __syncthreads();
    for (int s = 64; s > 0; s >>= 1) {
        if (t < s) { r0[t] += r0[t + s]; r1[t] += r1[t + s]; }
        __syncthreads();
    }
    if (t == 0) {
        out[ci * 2 + 0] = r0[0] + bo[0];
        out[ci * 2 + 1] = r1[0] + bo[1];
    }
}

// ---------------- launch ----------------
extern "C" void kernel_launch(void* const* d_in, const int* in_sizes, int n_in,
                              void* d_out, int out_size) {
    const int*   node_fea = (const int*)d_in[0];
    const float* edge_fea = (const float*)d_in[1];
    const int*   idx1 = (const int*)d_in[2];
    const int*   idx2 = (const int*)d_in[3];
    const int*   idx3 = (const int*)d_in[4];
    const float* emb  = (const float*)d_in[5];
    const float* Wf   = (const float*)d_in[6];
    const float* bf   = (const float*)d_in[7];
    const float* g1   = (const float*)d_in[8];
    const float* be1  = (const float*)d_in[9];
    const float* g2   = (const float*)d_in[10];
    const float* be2  = (const float*)d_in[11];
    const float* Wc   = (const float*)d_in[12];
    const float* bcv  = (const float*)d_in[13];
    const float* Wo   = (const float*)d_in[14];
    const float* bo   = (const float*)d_in[15];
    float* out = (float*)d_out;

    int N = in_sizes[0];
    int E = in_sizes[2];
    int C = out_size / 2;
    int nchunk = (E + 63) / 64;

    // order chosen so k_edge1 is the 4th launch (ncu capture slot)
    k_init<<<512, 256>>>();
    k_embed<<<(N * 64 + 255) / 256, 256>>>(node_fea, emb, N);

    for (int l = 0; l < 3; l++) {
        k_nodegemm<<<(N + 31) / 32, 256>>>(Wf, l, N);
        k_edge1<<<592, 256>>>(edge_fea, idx1, idx2, Wf, bf, l, E, nchunk);
        if (l == 0) k_deg<<<(E + 255) / 256, 256>>>(idx1, E);
        k_fin1<<<1, 128>>>(g1, be1, l, E);
        k_edge2<<<(E + 127) / 128, 256>>>(idx1, E);
        k_nodestats<<<256, 256>>>(N);
        k_fin2<<<1, 64>>>(g2, be2, l, N);
        k_nodeupd<<<(N * 64 + 255) / 256, 256>>>(N);
    }

    k_crys<<<(N * 16 + 255) / 256, 256>>>(idx3, N);
    k_head<<<C, 128>>>(Wc, bcv, Wo, bo, out, C);
}